// round 4
// baseline (speedup 1.0000x reference)
#include <cuda_runtime.h>
#include <cuda_fp16.h>
#include <cstdint>

// LoRAConv3d: out = conv3(x,[W;A]) -> (base+bias, low); out += 2*B@boxsum3(low)
// Implicit GEMM on mma.sync.m16n8k16 (f16 in, f32 acc).
// B=2, CIN=64, COUT=128, RANK=16, K=3^3, spatial 32^3, pad 1.

__device__ __half  xpad[2 * 34 * 34 * 34 * 64];   // padded NDHWC fp16
__device__ __half  wk[27 * 144 * 64];             // [off][n][c]
__device__ float   g_low[2 * 16 * 32768];

// ---------------- helpers ----------------
__device__ __forceinline__ uint32_t smem_u32(const void* p) {
    uint32_t a;
    asm("{ .reg .u64 t; cvta.to.shared.u64 t, %1; cvt.u32.u64 %0, t; }" : "=r"(a) : "l"(p));
    return a;
}
__device__ __forceinline__ void cp16(uint32_t dst, const void* src) {
    asm volatile("cp.async.cg.shared.global [%0], [%1], 16;" :: "r"(dst), "l"(src));
}
__device__ __forceinline__ void cp_commit() { asm volatile("cp.async.commit_group;"); }
template <int N> __device__ __forceinline__ void cp_wait() {
    asm volatile("cp.async.wait_group %0;" :: "n"(N) : "memory");
}
__device__ __forceinline__ void ldsm4(uint32_t* r, uint32_t addr) {
    asm volatile("ldmatrix.sync.aligned.m8n8.x4.shared.b16 {%0,%1,%2,%3}, [%4];"
                 : "=r"(r[0]), "=r"(r[1]), "=r"(r[2]), "=r"(r[3]) : "r"(addr));
}
__device__ __forceinline__ void ldsm2(uint32_t& b0, uint32_t& b1, uint32_t addr) {
    asm volatile("ldmatrix.sync.aligned.m8n8.x2.shared.b16 {%0,%1}, [%2];"
                 : "=r"(b0), "=r"(b1) : "r"(addr));
}
__device__ __forceinline__ void mma16816(float* c, const uint32_t* a,
                                         uint32_t b0, uint32_t b1) {
    asm volatile(
        "mma.sync.aligned.m16n8k16.row.col.f32.f16.f16.f32 "
        "{%0,%1,%2,%3}, {%4,%5,%6,%7}, {%8,%9}, {%0,%1,%2,%3};"
        : "+f"(c[0]), "+f"(c[1]), "+f"(c[2]), "+f"(c[3])
        : "r"(a[0]), "r"(a[1]), "r"(a[2]), "r"(a[3]), "r"(b0), "r"(b1));
}

// ---------------- prep kernels ----------------
// one block per (b, zp, yp) padded row-plane; writes ALL of xpad (zeros on border)
__global__ __launch_bounds__(256) void pad_x_kernel(const float* __restrict__ x) {
    int id = blockIdx.x;                       // 2*34*34
    int b = id / 1156, rem = id - b * 1156;
    int zp = rem / 34, yp = rem - zp * 34;
    const bool interior = (zp >= 1 && zp <= 32 && yp >= 1 && yp <= 32);
    __shared__ float s[2048];                  // [c][x]
    if (interior) {
        for (int i = threadIdx.x; i < 2048; i += 256) {
            int c = i >> 5, xx = i & 31;
            s[i] = x[((b * 64 + c) << 15) + ((zp - 1) << 10) + ((yp - 1) << 5) + xx];
        }
    }
    __syncthreads();
    __half* dst = xpad + (size_t)((b * 34 + zp) * 34 + yp) * 34 * 64;
    for (int i = threadIdx.x; i < 2176; i += 256) {
        int xi = i >> 6, c = i & 63;
        float v = (interior && xi >= 1 && xi <= 32) ? s[(c << 5) + (xi - 1)] : 0.f;
        dst[i] = __float2half(v);
    }
}

__global__ void prep_w_kernel(const float* __restrict__ weight,
                              const float* __restrict__ lora_A) {
    int i = blockIdx.x * 256 + threadIdx.x;    // 27*144*64
    if (i >= 27 * 144 * 64) return;
    int c = i & 63;
    int n = (i >> 6) % 144;
    int off = i / 9216;
    float v = (n < 128) ? weight[n * 1728 + c * 27 + off]
                        : lora_A[(n - 128) * 1728 + c * 27 + off];
    wk[i] = __float2half(v);
}

// ---------------- main conv: implicit GEMM on mma.sync ----------------
// per CTA: M=128 positions (1z x 4y x 32x), N=144, 27 offsets (K=64 each).
// 384 threads = 12 warps: 4 m-groups(32) x 3 n-groups(48).
// smem: A halo 612x144B; B 4-stage ring 4 x 144x144B; bias.
#define SA_BYTES   (612 * 144)                  // 88128
#define SB_STAGE   (144 * 144)                  // 20736
#define SB_OFF     SA_BYTES
#define SBIAS_OFF  (SA_BYTES + 4 * SB_STAGE)    // 171072
#define SMEM_TOTAL (SBIAS_OFF + 512)            // 171584

__device__ __forceinline__ void stage_B(uint32_t buf, int off, int tid) {
    const char* wb = (const char*)wk + (size_t)off * 18432;
#pragma unroll
    for (int i = tid; i < 1152; i += 384) {
        int row = i >> 3, k = i & 7;
        cp16(buf + row * 144 + k * 16, wb + row * 128 + k * 16);
    }
}

__global__ __launch_bounds__(384, 1) void conv_mma_kernel(
    const float* __restrict__ bias, float* __restrict__ out)
{
    extern __shared__ char smem[];
    const uint32_t sb = smem_u32(smem);
    const uint32_t sA = sb, sB = sb + SB_OFF;
    float* sbias = (float*)(smem + SBIAS_OFF);

    const int tid = threadIdx.x, lane = tid & 31, wid = tid >> 5;
    const int t = blockIdx.x;                  // 512 tiles
    const int b = t >> 8, z0 = (t >> 3) & 31, y0 = (t & 7) << 2;

    if (tid < 128) sbias[tid] = bias[tid];

    // stage A halo: rows r = (dz*6+yi)*34 + xi  (dz 0..2, yi 0..5, xi 0..33)
    {
        const char* xb = (const char*)xpad;
        for (int i = tid; i < 4896; i += 384) {
            int r = i >> 3, k = i & 7;
            int dz = r / 204, rem = r - dz * 204;
            int yi = rem / 34, xi = rem - yi * 34;
            size_t src = ((size_t)(((b * 34 + z0 + dz) * 34 + (y0 + yi)) * 34 + xi)) * 128
                         + k * 16;
            cp16(sA + r * 144 + k * 16, xb + src);
        }
    }
    stage_B(sB, 0, tid);
    cp_commit();                               // G0: A + B0
    stage_B(sB + SB_STAGE, 1, tid);
    cp_commit();                               // G1
    stage_B(sB + 2 * SB_STAGE, 2, tid);
    cp_commit();                               // G2

    const int warp_m = wid & 3;                // 0..3 -> m base 32*warp_m
    const int warp_n = wid >> 2;               // 0..2 -> n base 48*warp_n
    const int m0w = warp_m * 32;
    const int n0w = warp_n * 48;
    uint32_t laneA[2];
#pragma unroll
    for (int mi = 0; mi < 2; ++mi) {
        int m = m0w + mi * 16 + (lane & 15);
        int yi = m >> 5, xi = m & 31;
        laneA[mi] = (uint32_t)((yi * 34 + xi) * 144 + ((lane >> 4) << 4));
    }
    const uint32_t laneB = (uint32_t)((n0w + (lane & 7)) * 144 + ((lane >> 3) & 1) * 16);

    float acc[2][6][4];
#pragma unroll
    for (int mi = 0; mi < 2; ++mi)
#pragma unroll
        for (int nj = 0; nj < 6; ++nj)
#pragma unroll
            for (int q = 0; q < 4; ++q) acc[mi][nj][q] = 0.f;

    for (int off = 0; off < 27; ++off) {
        const int pend = 26 - off;
        if (pend >= 2)      cp_wait<2>();
        else if (pend == 1) cp_wait<1>();
        else                cp_wait<0>();
        __syncthreads();
        if (off + 3 < 27) {
            stage_B(sB + ((off + 3) & 3) * SB_STAGE, off + 3, tid);
            cp_commit();
        }
        const int dz = off / 9, r9 = off - dz * 9;
        const int dy = r9 / 3, dx = r9 - dy * 3;
        const uint32_t aoff = sA + (uint32_t)((dz * 204 + dy * 34 + dx) * 144);
        const uint32_t bbuf = sB + (off & 3) * SB_STAGE + laneB;

#pragma unroll
        for (int s = 0; s < 4; ++s) {
            uint32_t a0[4], a1[4];
            ldsm4(a0, aoff + laneA[0] + s * 32);
            ldsm4(a1, aoff + laneA[1] + s * 32);
            uint32_t bf[6][2];
#pragma unroll
            for (int nj = 0; nj < 6; ++nj)
                ldsm2(bf[nj][0], bf[nj][1], bbuf + nj * 1152 + s * 32);
#pragma unroll
            for (int nj = 0; nj < 6; ++nj) {
                mma16816(acc[0][nj], a0, bf[nj][0], bf[nj][1]);
                mma16816(acc[1][nj], a1, bf[nj][0], bf[nj][1]);
            }
        }
    }

    // epilogue
#pragma unroll
    for (int mi = 0; mi < 2; ++mi) {
        const int r0 = m0w + mi * 16 + (lane >> 2);
        const int r1 = r0 + 8;
        const int pos0 = z0 * 1024 + (y0 + (r0 >> 5)) * 32 + (r0 & 31);
        const int pos1 = z0 * 1024 + (y0 + (r1 >> 5)) * 32 + (r1 & 31);
#pragma unroll
        for (int nj = 0; nj < 6; ++nj) {
            const int c0 = n0w + nj * 8 + ((lane & 3) << 1);
#pragma unroll
            for (int q = 0; q < 4; ++q) {
                const int c = c0 + (q & 1);
                const int pos = (q < 2) ? pos0 : pos1;
                const float v = acc[mi][nj][q];
                if (c < 128)
                    out[(size_t)(b * 128 + c) * 32768 + pos] = v + sbias[c];
                else
                    g_low[(size_t)(b * 16 + (c - 128)) * 32768 + pos] = v;
            }
        }
    }
}

// ---------------- fused boxsum + lora apply ----------------
// block per (b, z): z-sum into smem, 2D boxsum from smem, then out += 2*B@ls.
#define LORA_SMEM (16 * 1024 * 4 + 2048 * 4)   // 73728
__global__ __launch_bounds__(1024) void lora_fused_kernel(
    const float* __restrict__ lora_B, float* __restrict__ out)
{
    extern __shared__ float lsm[];
    float* zsum = lsm;                 // [16][32*32]
    float* sB   = lsm + 16 * 1024;     // [128][16]

    const int id = blockIdx.x;         // 64 blocks
    const int z = id & 31, b = id >> 5;
    const int tid = threadIdx.x;
    const int y = tid >> 5, xx = tid & 31;

    for (int i = tid; i < 2048; i += 1024) sB[i] = lora_B[i];

#pragma unroll
    for (int r = 0; r < 16; ++r) {
        const float* base = g_low + ((size_t)(b * 16 + r) << 15);
        float s = 0.f;
#pragma unroll
        for (int zz = -1; zz <= 1; ++zz) {
            int zin = z + zz;
            if ((unsigned)zin < 32u) s += base[(zin << 10) + tid];
        }
        zsum[(r << 10) + tid] = s;
    }
    __syncthreads();

    float ls[16];
#pragma unroll
    for (int r = 0; r < 16; ++r) {
        float a = 0.f;
#pragma unroll
        for (int dy = -1; dy <= 1; ++dy) {
            int yy = y + dy;
            if ((unsigned)yy < 32u) {
                const float* row = zsum + (r << 10) + (yy << 5);
#pragma unroll
                for (int dx = -1; dx <= 1; ++dx) {
                    int xn = xx + dx;
                    if ((unsigned)xn < 32u) a += row[xn];
                }
            }
        }
        ls[r] = a;
    }

    const size_t posb = ((size_t)b * 128) * 32768 + (z << 10) + tid;
#pragma unroll 4
    for (int oc = 0; oc < 128; ++oc) {
        float d = 0.f;
#pragma unroll
        for (int r = 0; r < 16; ++r) d = fmaf(sB[oc * 16 + r], ls[r], d);
        size_t idx = posb + (size_t)oc * 32768;
        out[idx] += 2.0f * d;
    }
}

// ---------------- launch ----------------
extern "C" void kernel_launch(void* const* d_in, const int* in_sizes, int n_in,
                              void* d_out, int out_size)
{
    const float* x      = (const float*)d_in[0];
    const float* weight = (const float*)d_in[1];
    const float* bias   = (const float*)d_in[2];
    const float* lora_A = (const float*)d_in[3];
    const float* lora_B = (const float*)d_in[4];
    float* out = (float*)d_out;

    cudaFuncSetAttribute(conv_mma_kernel,
                         cudaFuncAttributeMaxDynamicSharedMemorySize, SMEM_TOTAL);
    cudaFuncSetAttribute(lora_fused_kernel,
                         cudaFuncAttributeMaxDynamicSharedMemorySize, LORA_SMEM);

    pad_x_kernel<<<2312, 256>>>(x);
    prep_w_kernel<<<(27 * 144 * 64 + 255) / 256, 256>>>(weight, lora_A);
    conv_mma_kernel<<<512, 384, SMEM_TOTAL>>>(bias, out);
    lora_fused_kernel<<<64, 1024, LORA_SMEM>>>(lora_B, out);
}

// round 5
// speedup vs baseline: 1.1499x; 1.1499x over previous
#include <cuda_runtime.h>
#include <cuda_fp16.h>
#include <cstdint>

// LoRAConv3d: out = conv3(x,[W;A]) -> (base+bias, low); out += 2*B@boxsum3(low)
// Implicit GEMM on mma.sync.m16n8k16 (f16 in, f32 acc).
// B=2, CIN=64, COUT=128, RANK=16, K=3^3, spatial 32^3, pad 1.

__device__ __half  xpad[2 * 34 * 34 * 34 * 64];   // padded NDHWC fp16
__device__ __half  wk[27 * 144 * 64];             // [off][n][c]
__device__ float   g_low[2 * 16 * 32768];

// ---------------- helpers ----------------
__device__ __forceinline__ uint32_t smem_u32(const void* p) {
    uint32_t a;
    asm("{ .reg .u64 t; cvta.to.shared.u64 t, %1; cvt.u32.u64 %0, t; }" : "=r"(a) : "l"(p));
    return a;
}
__device__ __forceinline__ void cp16(uint32_t dst, const void* src) {
    asm volatile("cp.async.cg.shared.global [%0], [%1], 16;" :: "r"(dst), "l"(src));
}
__device__ __forceinline__ void cp_commit() { asm volatile("cp.async.commit_group;"); }
template <int N> __device__ __forceinline__ void cp_wait() {
    asm volatile("cp.async.wait_group %0;" :: "n"(N) : "memory");
}
__device__ __forceinline__ void ldsm4(uint32_t* r, uint32_t addr) {
    asm volatile("ldmatrix.sync.aligned.m8n8.x4.shared.b16 {%0,%1,%2,%3}, [%4];"
                 : "=r"(r[0]), "=r"(r[1]), "=r"(r[2]), "=r"(r[3]) : "r"(addr));
}
__device__ __forceinline__ void ldsm2(uint32_t& b0, uint32_t& b1, uint32_t addr) {
    asm volatile("ldmatrix.sync.aligned.m8n8.x2.shared.b16 {%0,%1}, [%2];"
                 : "=r"(b0), "=r"(b1) : "r"(addr));
}
__device__ __forceinline__ void mma16816(float* c, const uint32_t* a,
                                         uint32_t b0, uint32_t b1) {
    asm volatile(
        "mma.sync.aligned.m16n8k16.row.col.f32.f16.f16.f32 "
        "{%0,%1,%2,%3}, {%4,%5,%6,%7}, {%8,%9}, {%0,%1,%2,%3};"
        : "+f"(c[0]), "+f"(c[1]), "+f"(c[2]), "+f"(c[3])
        : "r"(a[0]), "r"(a[1]), "r"(a[2]), "r"(a[3]), "r"(b0), "r"(b1));
}

// ---------------- prep kernels ----------------
// one block per (b, zp, yp) padded row-plane; writes ALL of xpad (zeros on border)
__global__ __launch_bounds__(256) void pad_x_kernel(const float* __restrict__ x) {
    int id = blockIdx.x;                       // 2*34*34
    int b = id / 1156, rem = id - b * 1156;
    int zp = rem / 34, yp = rem - zp * 34;
    const bool interior = (zp >= 1 && zp <= 32 && yp >= 1 && yp <= 32);
    __shared__ float s[2048];                  // [c][x]
    if (interior) {
        for (int i = threadIdx.x; i < 2048; i += 256) {
            int c = i >> 5, xx = i & 31;
            s[i] = x[((b * 64 + c) << 15) + ((zp - 1) << 10) + ((yp - 1) << 5) + xx];
        }
    }
    __syncthreads();
    __half* dst = xpad + (size_t)((b * 34 + zp) * 34 + yp) * 34 * 64;
    for (int i = threadIdx.x; i < 2176; i += 256) {
        int xi = i >> 6, c = i & 63;
        float v = (interior && xi >= 1 && xi <= 32) ? s[(c << 5) + (xi - 1)] : 0.f;
        dst[i] = __float2half(v);
    }
}

__global__ void prep_w_kernel(const float* __restrict__ weight,
                              const float* __restrict__ lora_A) {
    int i = blockIdx.x * 256 + threadIdx.x;    // 27*144*64
    if (i >= 27 * 144 * 64) return;
    int c = i & 63;
    int n = (i >> 6) % 144;
    int off = i / 9216;
    float v = (n < 128) ? weight[n * 1728 + c * 27 + off]
                        : lora_A[(n - 128) * 1728 + c * 27 + off];
    wk[i] = __float2half(v);
}

// ---------------- main conv: implicit GEMM on mma.sync ----------------
// per CTA: M=128 positions (1z x 4y x 32x), N=144, 27 offsets (K=64 each).
// 256 threads = 8 warps: 4 m-groups(32) x 2 n-groups(72).
#define SA_BYTES   (612 * 144)                 // 88128
#define SB_STRIDE  (144 * 144)                 // 20736
#define SB_OFF     SA_BYTES
#define SBIAS_OFF  (SA_BYTES + 2 * SB_STRIDE)  // 129600
#define SMEM_TOTAL (SBIAS_OFF + 512)           // 130112

__device__ __forceinline__ void stage_B(uint32_t buf, int off, int tid) {
    const char* wb = (const char*)wk + (size_t)off * 18432;
#pragma unroll
    for (int i = tid; i < 1152; i += 256) {
        int row = i >> 3, k = i & 7;
        cp16(buf + row * 144 + k * 16, wb + row * 128 + k * 16);
    }
}

__global__ __launch_bounds__(256, 1) void conv_mma_kernel(
    const float* __restrict__ bias, float* __restrict__ out)
{
    extern __shared__ char smem[];
    const uint32_t sb = smem_u32(smem);
    const uint32_t sA = sb, sB = sb + SB_OFF;
    float* sbias = (float*)(smem + SBIAS_OFF);

    const int tid = threadIdx.x, lane = tid & 31, wid = tid >> 5;
    const int t = blockIdx.x;                  // 512 tiles
    const int b = t >> 8, z0 = (t >> 3) & 31, y0 = (t & 7) << 2;

    if (tid < 128) sbias[tid] = bias[tid];

    // stage A halo: rows r = (dz*6+yi)*34 + xi  (dz 0..2, yi 0..5, xi 0..33)
    {
        const char* xb = (const char*)xpad;
        for (int i = tid; i < 4896; i += 256) {
            int r = i >> 3, k = i & 7;
            int dz = r / 204, rem = r - dz * 204;
            int yi = rem / 34, xi = rem - yi * 34;
            size_t src = ((size_t)(((b * 34 + z0 + dz) * 34 + (y0 + yi)) * 34 + xi)) * 128
                         + k * 16;
            cp16(sA + r * 144 + k * 16, xb + src);
        }
    }
    stage_B(sB, 0, tid);
    cp_commit();

    const int m0w = (wid >> 1) * 32;
    const int n0w = (wid & 1) * 72;
    uint32_t laneA[2];
#pragma unroll
    for (int mi = 0; mi < 2; ++mi) {
        int m = m0w + mi * 16 + (lane & 15);
        int yi = m >> 5, xi = m & 31;
        laneA[mi] = (uint32_t)((yi * 34 + xi) * 144 + ((lane >> 4) << 4));
    }
    // B ldsm4 lane address: covers a PAIR of n8 tiles (nj even/odd):
    // lanes 0-7: rows n0..7 koff0; 8-15: rows n0..7 koff16; 16-23: n8..15 koff0; 24-31: koff16
    const uint32_t laneB4 =
        (uint32_t)((n0w + ((lane >> 4) & 1) * 8 + (lane & 7)) * 144
                   + ((lane >> 3) & 1) * 16);
    // ldsm2 for nj=8 (rows n0w+64..71)
    const uint32_t laneB2 =
        (uint32_t)((n0w + 64 + (lane & 7)) * 144 + ((lane >> 3) & 1) * 16);

    float acc[2][9][4];
#pragma unroll
    for (int mi = 0; mi < 2; ++mi)
#pragma unroll
        for (int nj = 0; nj < 9; ++nj)
#pragma unroll
            for (int q = 0; q < 4; ++q) acc[mi][nj][q] = 0.f;

    for (int off = 0; off < 27; ++off) {
        cp_wait<0>();
        __syncthreads();
        if (off < 26) {
            stage_B(sB + ((off + 1) & 1) * SB_STRIDE, off + 1, tid);
            cp_commit();
        }
        const int dz = off / 9, r9 = off - dz * 9;
        const int dy = r9 / 3, dx = r9 - dy * 3;
        const uint32_t aoff = sA + (uint32_t)((dz * 204 + dy * 34 + dx) * 144);
        const uint32_t bb   = sB + (off & 1) * SB_STRIDE;
        const uint32_t b4   = bb + laneB4;
        const uint32_t b2   = bb + laneB2;

        uint32_t afr[2][8];     // [buf][2 m-frags x 4]
        uint32_t bfr[2][18];    // [buf][4 pairs x 4 + 2]

        // prologue: s=0 fragments
        ldsm4(&afr[0][0], aoff + laneA[0]);
        ldsm4(&afr[0][4], aoff + laneA[1]);
#pragma unroll
        for (int p = 0; p < 4; ++p) ldsm4(&bfr[0][p * 4], b4 + p * 2304);
        ldsm2(bfr[0][16], bfr[0][17], b2);

#pragma unroll
        for (int s = 0; s < 4; ++s) {
            const int cu = s & 1, nx = cu ^ 1;
            if (s < 3) {
                const uint32_t so = (uint32_t)((s + 1) * 32);
                ldsm4(&afr[nx][0], aoff + laneA[0] + so);
                ldsm4(&afr[nx][4], aoff + laneA[1] + so);
#pragma unroll
                for (int p = 0; p < 4; ++p) ldsm4(&bfr[nx][p * 4], b4 + p * 2304 + so);
                ldsm2(bfr[nx][16], bfr[nx][17], b2 + so);
            }
#pragma unroll
            for (int nj = 0; nj < 9; ++nj) {
                const uint32_t bv0 = (nj < 8) ? bfr[cu][(nj >> 1) * 4 + (nj & 1) * 2]
                                              : bfr[cu][16];
                const uint32_t bv1 = (nj < 8) ? bfr[cu][(nj >> 1) * 4 + (nj & 1) * 2 + 1]
                                              : bfr[cu][17];
                mma16816(acc[0][nj], &afr[cu][0], bv0, bv1);
                mma16816(acc[1][nj], &afr[cu][4], bv0, bv1);
            }
        }
    }

    // epilogue
#pragma unroll
    for (int mi = 0; mi < 2; ++mi) {
        const int r0 = m0w + mi * 16 + (lane >> 2);
        const int r1 = r0 + 8;
        const int pos0 = z0 * 1024 + (y0 + (r0 >> 5)) * 32 + (r0 & 31);
        const int pos1 = z0 * 1024 + (y0 + (r1 >> 5)) * 32 + (r1 & 31);
#pragma unroll
        for (int nj = 0; nj < 9; ++nj) {
            const int c0 = n0w + nj * 8 + ((lane & 3) << 1);
#pragma unroll
            for (int q = 0; q < 4; ++q) {
                const int c = c0 + (q & 1);
                const int pos = (q < 2) ? pos0 : pos1;
                const float v = acc[mi][nj][q];
                if (c < 128)
                    out[(size_t)(b * 128 + c) * 32768 + pos] = v + sbias[c];
                else
                    g_low[(size_t)(b * 16 + (c - 128)) * 32768 + pos] = v;
            }
        }
    }
}

// ---------------- fused boxsum + lora apply ----------------
// block per (b, z, group-of-32-oc): zsum in smem, 2D boxsum, out += 2*B@ls.
#define LORA_SMEM (16 * 1024 * 4 + 512 * 4)    // 67584
__global__ __launch_bounds__(1024) void lora_fused_kernel(
    const float* __restrict__ lora_B, float* __restrict__ out)
{
    extern __shared__ float lsm[];
    float* zsum = lsm;                 // [16][32*32]
    float* sB   = lsm + 16 * 1024;     // [32][16]

    const int id = blockIdx.x;         // 256 blocks: b*128 + z*4 + g
    const int g = id & 3, z = (id >> 2) & 31, b = id >> 7;
    const int tid = threadIdx.x;
    const int y = tid >> 5, xx = tid & 31;

    if (tid < 512) sB[tid] = lora_B[g * 512 + tid];

#pragma unroll
    for (int r = 0; r < 16; ++r) {
        const float* base = g_low + ((size_t)(b * 16 + r) << 15);
        float s = 0.f;
#pragma unroll
        for (int zz = -1; zz <= 1; ++zz) {
            int zin = z + zz;
            if ((unsigned)zin < 32u) s += base[(zin << 10) + tid];
        }
        zsum[(r << 10) + tid] = s;
    }
    __syncthreads();

    float ls[16];
#pragma unroll
    for (int r = 0; r < 16; ++r) {
        float a = 0.f;
#pragma unroll
        for (int dy = -1; dy <= 1; ++dy) {
            int yy = y + dy;
            if ((unsigned)yy < 32u) {
                const float* row = zsum + (r << 10) + (yy << 5);
#pragma unroll
                for (int dx = -1; dx <= 1; ++dx) {
                    int xn = xx + dx;
                    if ((unsigned)xn < 32u) a += row[xn];
                }
            }
        }
        ls[r] = a;
    }

    const size_t posb = ((size_t)(b * 128 + g * 32)) * 32768 + (z << 10) + tid;
#pragma unroll 4
    for (int oc = 0; oc < 32; ++oc) {
        float d = 0.f;
#pragma unroll
        for (int r = 0; r < 16; ++r) d = fmaf(sB[oc * 16 + r], ls[r], d);
        size_t idx = posb + (size_t)oc * 32768;
        out[idx] += 2.0f * d;
    }
}

// ---------------- launch ----------------
extern "C" void kernel_launch(void* const* d_in, const int* in_sizes, int n_in,
                              void* d_out, int out_size)
{
    const float* x      = (const float*)d_in[0];
    const float* weight = (const float*)d_in[1];
    const float* bias   = (const float*)d_in[2];
    const float* lora_A = (const float*)d_in[3];
    const float* lora_B = (const float*)d_in[4];
    float* out = (float*)d_out;

    cudaFuncSetAttribute(conv_mma_kernel,
                         cudaFuncAttributeMaxDynamicSharedMemorySize, SMEM_TOTAL);
    cudaFuncSetAttribute(lora_fused_kernel,
                         cudaFuncAttributeMaxDynamicSharedMemorySize, LORA_SMEM);

    pad_x_kernel<<<2312, 256>>>(x);
    prep_w_kernel<<<(27 * 144 * 64 + 255) / 256, 256>>>(weight, lora_A);
    conv_mma_kernel<<<512, 256, SMEM_TOTAL>>>(bias, out);
    lora_fused_kernel<<<256, 1024, LORA_SMEM>>>(lora_B, out);
}

// round 6
// speedup vs baseline: 1.3028x; 1.1329x over previous
#include <cuda_runtime.h>
#include <cuda_fp16.h>
#include <cstdint>

// LoRAConv3d: out = conv3(x,[W;A]) -> (base+bias, low); out += 2*B@boxsum3(low)
// Implicit GEMM on mma.sync.m16n8k16 (f16 in, f32 acc).
// B=2, CIN=64, COUT=128, RANK=16, K=3^3, spatial 32^3, pad 1.

__device__ __half  xpad[2 * 34 * 34 * 34 * 64];   // padded NDHWC fp16
__device__ __half  wk[27 * 144 * 64];             // [off][n][c]
__device__ float   g_low[2 * 16 * 32768];

// ---------------- helpers ----------------
__device__ __forceinline__ uint32_t smem_u32(const void* p) {
    uint32_t a;
    asm("{ .reg .u64 t; cvta.to.shared.u64 t, %1; cvt.u32.u64 %0, t; }" : "=r"(a) : "l"(p));
    return a;
}
__device__ __forceinline__ void cp16(uint32_t dst, const void* src) {
    asm volatile("cp.async.cg.shared.global [%0], [%1], 16;" :: "r"(dst), "l"(src));
}
__device__ __forceinline__ void cp_commit() { asm volatile("cp.async.commit_group;"); }
template <int N> __device__ __forceinline__ void cp_wait() {
    asm volatile("cp.async.wait_group %0;" :: "n"(N) : "memory");
}
__device__ __forceinline__ void ldsm4(uint32_t* r, uint32_t addr) {
    asm volatile("ldmatrix.sync.aligned.m8n8.x4.shared.b16 {%0,%1,%2,%3}, [%4];"
                 : "=r"(r[0]), "=r"(r[1]), "=r"(r[2]), "=r"(r[3]) : "r"(addr));
}
__device__ __forceinline__ void ldsm2(uint32_t& b0, uint32_t& b1, uint32_t addr) {
    asm volatile("ldmatrix.sync.aligned.m8n8.x2.shared.b16 {%0,%1}, [%2];"
                 : "=r"(b0), "=r"(b1) : "r"(addr));
}
__device__ __forceinline__ void mma16816(float* c, const uint32_t* a,
                                         uint32_t b0, uint32_t b1) {
    asm volatile(
        "mma.sync.aligned.m16n8k16.row.col.f32.f16.f16.f32 "
        "{%0,%1,%2,%3}, {%4,%5,%6,%7}, {%8,%9}, {%0,%1,%2,%3};"
        : "+f"(c[0]), "+f"(c[1]), "+f"(c[2]), "+f"(c[3])
        : "r"(a[0]), "r"(a[1]), "r"(a[2]), "r"(a[3]), "r"(b0), "r"(b1));
}

// ---------------- prep kernels ----------------
__global__ __launch_bounds__(256) void pad_x_kernel(const float* __restrict__ x) {
    int id = blockIdx.x;                       // 2*34*34
    int b = id / 1156, rem = id - b * 1156;
    int zp = rem / 34, yp = rem - zp * 34;
    const bool interior = (zp >= 1 && zp <= 32 && yp >= 1 && yp <= 32);
    __shared__ float s[2048];                  // [c][x]
    if (interior) {
        for (int i = threadIdx.x; i < 2048; i += 256) {
            int c = i >> 5, xx = i & 31;
            s[i] = x[((b * 64 + c) << 15) + ((zp - 1) << 10) + ((yp - 1) << 5) + xx];
        }
    }
    __syncthreads();
    __half* dst = xpad + (size_t)((b * 34 + zp) * 34 + yp) * 34 * 64;
    for (int i = threadIdx.x; i < 2176; i += 256) {
        int xi = i >> 6, c = i & 63;
        float v = (interior && xi >= 1 && xi <= 32) ? s[(c << 5) + (xi - 1)] : 0.f;
        dst[i] = __float2half(v);
    }
}

__global__ void prep_w_kernel(const float* __restrict__ weight,
                              const float* __restrict__ lora_A) {
    int i = blockIdx.x * 256 + threadIdx.x;    // 27*144*64
    if (i >= 27 * 144 * 64) return;
    int c = i & 63;
    int n = (i >> 6) % 144;
    int off = i / 9216;
    float v = (n < 128) ? weight[n * 1728 + c * 27 + off]
                        : lora_A[(n - 128) * 1728 + c * 27 + off];
    wk[i] = __float2half(v);
}

// ---------------- main conv: implicit GEMM on mma.sync ----------------
// per CTA: M=128 positions (2z x 4y x 16x), N=144, 27 offsets (K=64 each).
// halo: 4z x 6y x 18x = 432 rows x 144B. 2 CTAs/SM.
#define SA_BYTES   (432 * 144)                 // 62208
#define SB_STRIDE  (144 * 144)                 // 20736
#define SB_OFF     SA_BYTES
#define SBIAS_OFF  (SA_BYTES + 2 * SB_STRIDE)  // 103680
#define SMEM_TOTAL (SBIAS_OFF + 512)           // 104192

__device__ __forceinline__ void stage_B(uint32_t buf, int off, int tid) {
    const char* wb = (const char*)wk + (size_t)off * 18432;
#pragma unroll
    for (int i = tid; i < 1152; i += 256) {
        int row = i >> 3, k = i & 7;
        cp16(buf + row * 144 + k * 16, wb + row * 128 + k * 16);
    }
}

__global__ __launch_bounds__(256, 2) void conv_mma_kernel(
    const float* __restrict__ bias, float* __restrict__ out)
{
    extern __shared__ char smem[];
    const uint32_t sb = smem_u32(smem);
    const uint32_t sA = sb, sB = sb + SB_OFF;
    float* sbias = (float*)(smem + SBIAS_OFF);

    const int tid = threadIdx.x, lane = tid & 31, wid = tid >> 5;
    const int t = blockIdx.x;                  // 512 tiles
    const int b  = t >> 8;
    const int r  = t & 255;                    // 16 z-tiles x 8 y-tiles x 2 x-tiles
    const int z0 = (r >> 4) * 2;
    const int y0 = ((r >> 1) & 7) * 4;
    const int x0 = (r & 1) * 16;

    if (tid < 128) sbias[tid] = bias[tid];

    // stage A halo: rows rr = (dz*6+yi)*18 + xi  (dz 0..3, yi 0..5, xi 0..17)
    {
        const char* xb = (const char*)xpad;
        for (int i = tid; i < 3456; i += 256) {
            int rr = i >> 3, k = i & 7;
            int dz = rr / 108, rem = rr - dz * 108;
            int yi = rem / 18, xi = rem - yi * 18;
            size_t src = ((size_t)(((b * 34 + z0 + dz) * 34 + (y0 + yi)) * 34 + (x0 + xi)))
                         * 128 + k * 16;
            cp16(sA + rr * 144 + k * 16, xb + src);
        }
    }
    stage_B(sB, 0, tid);
    cp_commit();

    const int m0w = (wid >> 1) * 32;
    const int n0w = (wid & 1) * 72;
    uint32_t laneA[2];
#pragma unroll
    for (int mi = 0; mi < 2; ++mi) {
        int m = m0w + mi * 16 + (lane & 15);
        int zi = m >> 6, yi = (m >> 4) & 3, xi = m & 15;
        laneA[mi] = (uint32_t)((zi * 108 + yi * 18 + xi) * 144 + ((lane >> 4) << 4));
    }
    const uint32_t laneB4 =
        (uint32_t)((n0w + ((lane >> 4) & 1) * 8 + (lane & 7)) * 144
                   + ((lane >> 3) & 1) * 16);
    const uint32_t laneB2 =
        (uint32_t)((n0w + 64 + (lane & 7)) * 144 + ((lane >> 3) & 1) * 16);

    float acc[2][9][4];
#pragma unroll
    for (int mi = 0; mi < 2; ++mi)
#pragma unroll
        for (int nj = 0; nj < 9; ++nj)
#pragma unroll
            for (int q = 0; q < 4; ++q) acc[mi][nj][q] = 0.f;

    for (int off = 0; off < 27; ++off) {
        cp_wait<0>();
        __syncthreads();
        if (off < 26) {
            stage_B(sB + ((off + 1) & 1) * SB_STRIDE, off + 1, tid);
            cp_commit();
        }
        const int dz = off / 9, r9 = off - dz * 9;
        const int dy = r9 / 3, dx = r9 - dy * 3;
        const uint32_t aoff = sA + (uint32_t)((dz * 108 + dy * 18 + dx) * 144);
        const uint32_t bb   = sB + (off & 1) * SB_STRIDE;
        const uint32_t b4   = bb + laneB4;
        const uint32_t b2   = bb + laneB2;

#pragma unroll
        for (int s = 0; s < 4; ++s) {
            const uint32_t so = (uint32_t)(s * 32);
            uint32_t a0[4], a1[4];
            ldsm4(a0, aoff + laneA[0] + so);
            ldsm4(a1, aoff + laneA[1] + so);
            uint32_t bf[18];
#pragma unroll
            for (int p = 0; p < 4; ++p) ldsm4(&bf[p * 4], b4 + p * 2304 + so);
            ldsm2(bf[16], bf[17], b2 + so);
#pragma unroll
            for (int nj = 0; nj < 9; ++nj) {
                const uint32_t bv0 = (nj < 8) ? bf[(nj >> 1) * 4 + (nj & 1) * 2] : bf[16];
                const uint32_t bv1 = (nj < 8) ? bf[(nj >> 1) * 4 + (nj & 1) * 2 + 1] : bf[17];
                mma16816(acc[0][nj], a0, bv0, bv1);
                mma16816(acc[1][nj], a1, bv0, bv1);
            }
        }
    }

    // epilogue
#pragma unroll
    for (int mi = 0; mi < 2; ++mi) {
        const int r0 = m0w + mi * 16 + (lane >> 2);
        const int r1 = r0 + 8;
        const int pos0 = (z0 + (r0 >> 6)) * 1024 + (y0 + ((r0 >> 4) & 3)) * 32
                         + x0 + (r0 & 15);
        const int pos1 = (z0 + (r1 >> 6)) * 1024 + (y0 + ((r1 >> 4) & 3)) * 32
                         + x0 + (r1 & 15);
#pragma unroll
        for (int nj = 0; nj < 9; ++nj) {
            const int c0 = n0w + nj * 8 + ((lane & 3) << 1);
#pragma unroll
            for (int q = 0; q < 4; ++q) {
                const int c = c0 + (q & 1);
                const int pos = (q < 2) ? pos0 : pos1;
                const float v = acc[mi][nj][q];
                if (c < 128)
                    out[(size_t)(b * 128 + c) * 32768 + pos] = v + sbias[c];
                else
                    g_low[(size_t)(b * 16 + (c - 128)) * 32768 + pos] = v;
            }
        }
    }
}

// ---------------- fused boxsum + lora apply ----------------
#define LORA_SMEM (16 * 1024 * 4 + 512 * 4)    // 67584
__global__ __launch_bounds__(1024) void lora_fused_kernel(
    const float* __restrict__ lora_B, float* __restrict__ out)
{
    extern __shared__ float lsm[];
    float* zsum = lsm;                 // [16][32*32]
    float* sB   = lsm + 16 * 1024;     // [32][16]

    const int id = blockIdx.x;         // 256 blocks: b*128 + z*4 + g
    const int g = id & 3, z = (id >> 2) & 31, b = id >> 7;
    const int tid = threadIdx.x;
    const int y = tid >> 5, xx = tid & 31;

    if (tid < 512) sB[tid] = lora_B[g * 512 + tid];

#pragma unroll
    for (int r = 0; r < 16; ++r) {
        const float* base = g_low + ((size_t)(b * 16 + r) << 15);
        float s = 0.f;
#pragma unroll
        for (int zz = -1; zz <= 1; ++zz) {
            int zin = z + zz;
            if ((unsigned)zin < 32u) s += base[(zin << 10) + tid];
        }
        zsum[(r << 10) + tid] = s;
    }
    __syncthreads();

    float ls[16];
#pragma unroll
    for (int r = 0; r < 16; ++r) {
        float a = 0.f;
#pragma unroll
        for (int dy = -1; dy <= 1; ++dy) {
            int yy = y + dy;
            if ((unsigned)yy < 32u) {
                const float* row = zsum + (r << 10) + (yy << 5);
#pragma unroll
                for (int dx = -1; dx <= 1; ++dx) {
                    int xn = xx + dx;
                    if ((unsigned)xn < 32u) a += row[xn];
                }
            }
        }
        ls[r] = a;
    }

    const size_t posb = ((size_t)(b * 128 + g * 32)) * 32768 + (z << 10) + tid;
#pragma unroll 4
    for (int oc = 0; oc < 32; ++oc) {
        float d = 0.f;
#pragma unroll
        for (int r = 0; r < 16; ++r) d = fmaf(sB[oc * 16 + r], ls[r], d);
        size_t idx = posb + (size_t)oc * 32768;
        out[idx] += 2.0f * d;
    }
}

// ---------------- launch ----------------
extern "C" void kernel_launch(void* const* d_in, const int* in_sizes, int n_in,
                              void* d_out, int out_size)
{
    const float* x      = (const float*)d_in[0];
    const float* weight = (const float*)d_in[1];
    const float* bias   = (const float*)d_in[2];
    const float* lora_A = (const float*)d_in[3];
    const float* lora_B = (const float*)d_in[4];
    float* out = (float*)d_out;

    cudaFuncSetAttribute(conv_mma_kernel,
                         cudaFuncAttributeMaxDynamicSharedMemorySize, SMEM_TOTAL);
    cudaFuncSetAttribute(lora_fused_kernel,
                         cudaFuncAttributeMaxDynamicSharedMemorySize, LORA_SMEM);

    pad_x_kernel<<<2312, 256>>>(x);
    prep_w_kernel<<<(27 * 144 * 64 + 255) / 256, 256>>>(weight, lora_A);
    conv_mma_kernel<<<512, 256, SMEM_TOTAL>>>(bias, out);
    lora_fused_kernel<<<256, 1024, LORA_SMEM>>>(lora_B, out);
}